// round 6
// baseline (speedup 1.0000x reference)
#include <cuda_runtime.h>
#include <cstdint>

// rgb: (1, 3, 2048, 2048) fp32; num_bins=4, kernel_size=3, pixel_size=32
#define H       2048
#define W       2048
#define PS      32
#define OB      (H / PS)        // 64
#define NB      4
#define PLANE   (H * W)
#define NCELL   (OB * OB)       // 4096

// cell colors: [ch][cell]
__device__ float g_table[3 * NCELL];

// ---------------------------------------------------------------------------
// Kernel A: one warp per cell (proven in R3). Lanes 0..8 load the 3x3 window,
// exact IEEE binning, ballot/popc counts (exact argmax tie-break), butterfly
// reduce, lane 0 writes the 3 channel colors to the table.
// ---------------------------------------------------------------------------
__global__ __launch_bounds__(256)
void cell_color_kernel(const float* __restrict__ rgb) {
    const int cell = blockIdx.x * 8 + (threadIdx.x >> 5);  // 0 .. 4095
    const int lane = threadIdx.x & 31;
    const int ow = cell & (OB - 1);
    const int oh = cell >> 6;

    float r = 0.f, g = 0.f, b = 0.f;
    int bin = -1;

    if (lane < 9) {
        const int dh = lane / 3 - 1;
        const int dw = lane - (lane / 3) * 3 - 1;
        const int h = oh * PS + dh;
        const int w = ow * PS + dw;
        if (h >= 0 && w >= 0) {          // high edge never OOB (max center 2016)
            const float* p = rgb + (size_t)h * W + w;
            r = __ldg(p);
            g = __ldg(p + PLANE);
            b = __ldg(p + 2 * PLANE);
            // bin = int( ((r+g+b)/3) / 256 * 4 ), IEEE ops to match JAX exactly
            const float s    = __fadd_rn(__fadd_rn(r, g), b);
            const float mean = __fdiv_rn(s, 3.0f);
            const float v    = __fmul_rn(__fdiv_rn(mean, 256.0f), 4.0f);
            bin = (int)v;
            if (bin > NB - 1) bin = NB - 1;
        }
    }

    const int c0 = __popc(__ballot_sync(0xFFFFFFFFu, bin == 0));
    const int c1 = __popc(__ballot_sync(0xFFFFFFFFu, bin == 1));
    const int c2 = __popc(__ballot_sync(0xFFFFFFFFu, bin == 2));
    const int c3 = __popc(__ballot_sync(0xFFFFFFFFu, bin == 3));

    int best = 0, bc = c0;
    if (c1 > bc) { best = 1; bc = c1; }
    if (c2 > bc) { best = 2; bc = c2; }
    if (c3 > bc) { best = 3; bc = c3; }

    float rs = (bin == best) ? r : 0.f;
    float gs = (bin == best) ? g : 0.f;
    float bs = (bin == best) ? b : 0.f;
    #pragma unroll
    for (int off = 16; off > 0; off >>= 1) {
        rs += __shfl_xor_sync(0xFFFFFFFFu, rs, off);
        gs += __shfl_xor_sync(0xFFFFFFFFu, gs, off);
        bs += __shfl_xor_sync(0xFFFFFFFFu, bs, off);
    }

    if (lane == 0) {
        const float imax = (float)bc;
        g_table[0 * NCELL + cell] = __fdiv_rn(rs, imax);
        g_table[1 * NCELL + cell] = __fdiv_rn(gs, imax);
        g_table[2 * NCELL + cell] = __fdiv_rn(bs, imax);
    }
}

// ---------------------------------------------------------------------------
// Kernel B: TMA bulk-store fill. One block per (ch, oh, row-group-of-8):
// 3 * 64 * 4 = 768 blocks. Build the 8KB output-row pattern (64 cell colors
// expanded x32) in smem ONCE, then issue 8 cp.async.bulk 8KB stores — one per
// output row (each 2048-float row is contiguous & 8KB-aligned in gmem, and
// all 32 rows of a cell-row share the same pattern). Bypasses L1 and the SM
// store-issue path entirely.
// ---------------------------------------------------------------------------
__global__ __launch_bounds__(256)
void fill_tma_kernel(float* __restrict__ out) {
    __shared__ __align__(128) float s_row[W];   // 8KB

    const int g   = blockIdx.x;          // 0..767
    const int ch  = g >> 8;              // /256
    const int rem = g & 255;
    const int oh  = rem >> 2;            // /4
    const int rg  = rem & 3;             // row group 0..3

    // Build the row pattern: thread t fills float4 slots t and t+256.
    const float* __restrict__ tab = g_table + ch * NCELL + oh * OB;
    const int t = threadIdx.x;
    {
        const float c0 = __ldg(tab + (t >> 3));             // slot t   -> cell t/8
        const float c1 = __ldg(tab + ((t + 256) >> 3));     // slot t+256
        reinterpret_cast<float4*>(s_row)[t]       = make_float4(c0, c0, c0, c0);
        reinterpret_cast<float4*>(s_row)[t + 256] = make_float4(c1, c1, c1, c1);
    }
    __syncthreads();

    if (t == 0) {
        // make generic-proxy smem writes visible to the async proxy
        asm volatile("fence.proxy.async.shared::cta;" ::: "memory");

        uint32_t src;
        asm("{ .reg .u64 a; cvta.to.shared.u64 a, %1; cvt.u32.u64 %0, a; }"
            : "=r"(src) : "l"(s_row));

        const int row0 = oh * PS + rg * 8;
        float* dst0 = out + (size_t)ch * PLANE + (size_t)row0 * W;
        #pragma unroll
        for (int r = 0; r < 8; r++) {
            float* dst = dst0 + (size_t)r * W;
            asm volatile(
                "cp.async.bulk.global.shared::cta.bulk_group [%0], [%1], %2;"
                :: "l"(dst), "r"(src), "r"((uint32_t)(W * sizeof(float)))
                : "memory");
        }
        asm volatile("cp.async.bulk.commit_group;" ::: "memory");
        asm volatile("cp.async.bulk.wait_group 0;" ::: "memory");
    }
}

extern "C" void kernel_launch(void* const* d_in, const int* in_sizes, int n_in,
                              void* d_out, int out_size) {
    const float* rgb = (const float*)d_in[0];
    float* out = (float*)d_out;
    cell_color_kernel<<<NCELL / 8, 256>>>(rgb);
    fill_tma_kernel<<<3 * OB * 4, 256>>>(out);
}

// round 7
// speedup vs baseline: 1.2031x; 1.2031x over previous
#include <cuda_runtime.h>

// rgb: (1, 3, 2048, 2048) fp32; num_bins=4, kernel_size=3, pixel_size=32
#define H       2048
#define W       2048
#define PS      32
#define OB      (H / PS)        // 64
#define NB      4
#define PLANE   (H * W)
#define NCELL   (OB * OB)       // 4096

// ---------------------------------------------------------------------------
// Fused, 2 warps per cell (cell x half). Each warp independently:
//   1) lanes 0..8 load the 3x3 window (3 parallel LDGs each)
//   2) exact bin via IEEE ops; counts via ballot/popc (exact argmax tie-break)
//   3) butterfly shuffle-reduce -> every lane holds winning-bin sums
//   4) stores its 16-row half: 4 rows x 3 channels = 12 independent STG.128
// 8192 warps total: half of R5's redundant preamble work, same store
// parallelism. Warp store = 4 x 128B coalesced segments per STG.
// ---------------------------------------------------------------------------
__global__ __launch_bounds__(256)
void pixel_effect_fused(const float* __restrict__ rgb, float* __restrict__ out) {
    const int gwarp = blockIdx.x * 8 + (threadIdx.x >> 5);  // 0 .. 8191
    const int lane  = threadIdx.x & 31;
    const int cell  = gwarp >> 1;        // 0 .. 4095
    const int half  = gwarp & 1;         // 16-row half 0/1
    const int ow = cell & (OB - 1);
    const int oh = cell >> 6;

    float r = 0.f, g = 0.f, b = 0.f;
    int bin = -1;

    if (lane < 9) {
        const int dh = lane / 3 - 1;
        const int dw = lane - (lane / 3) * 3 - 1;
        const int h = oh * PS + dh;
        const int w = ow * PS + dw;
        if (h >= 0 && w >= 0) {          // high edge never OOB (max center 2016)
            const float* p = rgb + (size_t)h * W + w;
            r = __ldg(p);
            g = __ldg(p + PLANE);
            b = __ldg(p + 2 * PLANE);
            // bin = int( ((r+g+b)/3) / 256 * 4 ), IEEE ops to match JAX exactly
            const float s    = __fadd_rn(__fadd_rn(r, g), b);
            const float mean = __fdiv_rn(s, 3.0f);
            const float v    = __fmul_rn(__fdiv_rn(mean, 256.0f), 4.0f);
            bin = (int)v;
            if (bin > NB - 1) bin = NB - 1;
        }
    }

    // exact per-bin counts (uniform across warp)
    const int c0 = __popc(__ballot_sync(0xFFFFFFFFu, bin == 0));
    const int c1 = __popc(__ballot_sync(0xFFFFFFFFu, bin == 1));
    const int c2 = __popc(__ballot_sync(0xFFFFFFFFu, bin == 2));
    const int c3 = __popc(__ballot_sync(0xFFFFFFFFu, bin == 3));

    // argmax, first-max tie-break (matches jnp.argmax)
    int best = 0, bc = c0;
    if (c1 > bc) { best = 1; bc = c1; }
    if (c2 > bc) { best = 2; bc = c2; }
    if (c3 > bc) { best = 3; bc = c3; }

    // butterfly reduce: all lanes end with the winning bin's sums
    float rs = (bin == best) ? r : 0.f;
    float gs = (bin == best) ? g : 0.f;
    float bs = (bin == best) ? b : 0.f;
    #pragma unroll
    for (int off = 16; off > 0; off >>= 1) {
        rs += __shfl_xor_sync(0xFFFFFFFFu, rs, off);
        gs += __shfl_xor_sync(0xFFFFFFFFu, gs, off);
        bs += __shfl_xor_sync(0xFFFFFFFFu, bs, off);
    }

    const float imax = (float)bc;                 // uniform
    const float cr = __fdiv_rn(rs, imax);
    const float cg = __fdiv_rn(gs, imax);
    const float cb = __fdiv_rn(bs, imax);

    const float4 vr = make_float4(cr, cr, cr, cr);
    const float4 vg = make_float4(cg, cg, cg, cg);
    const float4 vb = make_float4(cb, cb, cb, cb);

    // half fill: lane -> col4 = lane&7, rows half*16 + (lane>>3)*4 + {0..3}
    const int c4    = lane & 7;
    const int rbase = half * 16 + (lane >> 3) * 4;
    const size_t base = (size_t)(oh * PS + rbase) * W + (size_t)ow * PS + (size_t)c4 * 4;

    float* p0 = out + base;
    #pragma unroll
    for (int i = 0; i < 4; i++) {
        float* p = p0 + (size_t)i * W;
        *reinterpret_cast<float4*>(p)                     = vr;
        *reinterpret_cast<float4*>(p + (size_t)PLANE)     = vg;
        *reinterpret_cast<float4*>(p + (size_t)2 * PLANE) = vb;
    }
}

extern "C" void kernel_launch(void* const* d_in, const int* in_sizes, int n_in,
                              void* d_out, int out_size) {
    const float* rgb = (const float*)d_in[0];
    float* out = (float*)d_out;
    pixel_effect_fused<<<NCELL * 2 / 8, 256>>>(rgb, out);
}